// round 9
// baseline (speedup 1.0000x reference)
#include <cuda_runtime.h>
#include <math_constants.h>

// ChamferDistance: x1,x2 = [B=8, N=M=8192, 3] fp32.
// out = [ loss (1) | dist1 (B*N) | dist2 (B*M) ]
//
// R9: x-binned pruned NN search.
//  K_zero:    zero bin counters
//  K_hist:    histogram of x into 256 bins per (cloud,batch)
//  K_prefix:  warp-scan exclusive prefix -> bin starts + scatter cursors
//  K_scatter: bin-grouped scatter of points as float4{x,y,z,idx}
//  K_nn:      per-CTA (256 bin-ordered A pts): seed scan of bins +-SEED,
//             then bound-derived residual scan. Packed-f32x2 inner loop.
//  2-stage deterministic loss reduction.
// Correctness: true NN lies within |dx| <= sqrt(u) <= R of the query; clamped
// edge bins extend to +-inf; empty seed -> u=INF -> full scan. Min over a set
// of bit-identical e values is order/duplicate invariant -> deterministic.

constexpr int Bc = 8;
constexpr int Nc = 8192;
constexpr int NBINS = 256;
constexpr float XLO = -4.5f;
constexpr float INV_H = NBINS / 9.0f;         // bins over [-4.5, 4.5]
constexpr int NCB = 16;                       // cloud(2) * batch(8)
constexpr int SEED = 4;                       // seed half-width in bins
constexpr int NN_THREADS = 256;
constexpr int NN_GRID = NCB * (Nc / NN_THREADS);   // 512

__device__ float4 g_scat[NCB][Nc];            // bin-grouped points
__device__ int g_cnt[NCB][NBINS];
__device__ int g_start[NCB][NBINS + 1];
__device__ int g_cur[NCB][NBINS];
__device__ float g_partials[128];

__device__ __forceinline__ unsigned long long pk2(float lo, float hi) {
    unsigned long long r;
    asm("mov.b64 %0, {%1, %2};" : "=l"(r) : "f"(lo), "f"(hi));
    return r;
}
__device__ __forceinline__ unsigned long long ffma2(unsigned long long a,
                                                    unsigned long long b,
                                                    unsigned long long c) {
    unsigned long long d;
    asm("fma.rn.f32x2 %0, %1, %2, %3;" : "=l"(d) : "l"(a), "l"(b), "l"(c));
    return d;
}
__device__ __forceinline__ void upk2(unsigned long long v, float& lo, float& hi) {
    asm("mov.b64 {%0, %1}, %2;" : "=f"(lo), "=f"(hi) : "l"(v));
}

__device__ __forceinline__ int bin_of(float x) {
    float v = (x - XLO) * INV_H;
    v = fminf(fmaxf(v, 0.0f), 255.0f);        // handles +-inf safely
    return (int)v;
}

// ---------------- binning kernels ----------------

__global__ void __launch_bounds__(512) zero_kernel() {
    int* p = &g_cnt[0][0];
#pragma unroll
    for (int k = 0; k < 8; k++) p[k * 512 + threadIdx.x] = 0;
}

__global__ void __launch_bounds__(512)
hist_kernel(const float* __restrict__ x1, const float* __restrict__ x2) {
    const int gid = blockIdx.x * 512 + threadIdx.x;      // [0, 131072)
    const int c = gid >> 16;
    const int r = gid & 65535;
    const int b = r >> 13;
    const int i = r & 8191;
    const float* src = c ? x2 : x1;
    const float x = src[((size_t)b * Nc + i) * 3];
    atomicAdd(&g_cnt[c * 8 + b][bin_of(x)], 1);
}

__global__ void __launch_bounds__(512) prefix_kernel() {
    const int cb = threadIdx.x >> 5;           // 16 warps, one per (cloud,batch)
    const int lane = threadIdx.x & 31;
    int cnt[8];
    int s = 0;
#pragma unroll
    for (int k = 0; k < 8; k++) { cnt[k] = g_cnt[cb][lane * 8 + k]; s += cnt[k]; }
    int run = s;
#pragma unroll
    for (int d = 1; d < 32; d <<= 1) {
        int v = __shfl_up_sync(0xffffffffu, run, d);
        if (lane >= d) run += v;
    }
    int excl = run - s;
#pragma unroll
    for (int k = 0; k < 8; k++) {
        g_start[cb][lane * 8 + k] = excl;
        g_cur[cb][lane * 8 + k] = excl;
        excl += cnt[k];
    }
    if (lane == 31) g_start[cb][NBINS] = excl;
}

__global__ void __launch_bounds__(512)
scatter_kernel(const float* __restrict__ x1, const float* __restrict__ x2) {
    const int gid = blockIdx.x * 512 + threadIdx.x;
    const int c = gid >> 16;
    const int r = gid & 65535;
    const int b = r >> 13;
    const int i = r & 8191;
    const float* src = c ? x2 : x1;
    const float* p = src + ((size_t)b * Nc + i) * 3;
    const float x = p[0], y = p[1], z = p[2];
    const int cb = c * 8 + b;
    const int pos = atomicAdd(&g_cur[cb][bin_of(x)], 1);
    g_scat[cb][pos] = make_float4(x, y, z, __int_as_float(i));
}

// ---------------- NN kernel ----------------

// Scan candidates [lo, hi) of scat via packed smem tiles. lo/hi CTA-uniform.
__device__ __forceinline__ void scan_range(
    int lo, int hi, const float4* __restrict__ scat, float* tile, int tid,
    unsigned long long axp, unsigned long long ayp, unsigned long long azp,
    float& eminE, float& eminO)
{
    for (int base = lo; base < hi; base += NN_THREADS) {
        __syncthreads();                       // protect previous tile reads
        const int idx = base + tid;
        float bx = 0.0f, by = 0.0f, bz = 0.0f, n2 = 1e30f;   // sentinel
        if (idx < hi) {
            const float4 q = scat[idx];
            bx = q.x; by = q.y; bz = q.z;
            n2 = fmaf(bx, bx, fmaf(by, by, bz * bz));
        }
        const int p = tid >> 1, eo = tid & 1;
        tile[p * 8 + 0 + eo] = -2.0f * bx;
        tile[p * 8 + 2 + eo] = -2.0f * by;
        tile[p * 8 + 4 + eo] = -2.0f * bz;
        tile[p * 8 + 6 + eo] = n2;
        __syncthreads();

        const ulonglong2* sp = reinterpret_cast<const ulonglong2*>(tile);
#pragma unroll 8
        for (int j = 0; j < NN_THREADS / 2; j++) {
            const ulonglong2 c0 = sp[2 * j];        // {bx2e,bx2o}{by2e,by2o}
            const ulonglong2 c1 = sp[2 * j + 1];    // {bz2e,bz2o}{n2e,n2o}
            unsigned long long e = ffma2(axp, c0.x, c1.y);
            e = ffma2(ayp, c0.y, e);
            e = ffma2(azp, c1.x, e);
            float flo, fhi;
            upk2(e, flo, fhi);
            eminE = fminf(eminE, flo);
            eminO = fminf(eminO, fhi);
        }
    }
}

__global__ void __launch_bounds__(NN_THREADS)
nn_kernel(float* __restrict__ dist1, float* __restrict__ dist2)
{
    __shared__ __align__(16) float tile[(NN_THREADS / 2) * 8];
    __shared__ float sred[NN_THREADS];

    const int tid = threadIdx.x;
    const int cbA = blockIdx.x >> 5;          // 32 CTAs per (cloud,batch)
    const int seg = blockIdx.x & 31;
    const int cbB = cbA ^ 8;                  // opposite cloud, same batch
    const int dir = cbA >> 3;                 // 0: A=x1, 1: A=x2
    const int b = cbA & 7;

    const float4 A = g_scat[cbA][seg * NN_THREADS + tid];
    const float ax = A.x, ay = A.y, az = A.z;
    const int oi = __float_as_int(A.w);
    const float n1 = fmaf(ax, ax, fmaf(ay, ay, az * az));
    const unsigned long long axp = pk2(ax, ax);
    const unsigned long long ayp = pk2(ay, ay);
    const unsigned long long azp = pk2(az, az);
    float eminE = CUDART_INF_F, eminO = CUDART_INF_F;

    // CTA x-range (amin, amax)
    sred[tid] = ax;
    __syncthreads();
    for (int w = NN_THREADS / 2; w > 0; w >>= 1) {
        if (tid < w) sred[tid] = fminf(sred[tid], sred[tid + w]);
        __syncthreads();
    }
    const float amin = sred[0];
    __syncthreads();
    sred[tid] = ax;
    __syncthreads();
    for (int w = NN_THREADS / 2; w > 0; w >>= 1) {
        if (tid < w) sred[tid] = fmaxf(sred[tid], sred[tid + w]);
        __syncthreads();
    }
    const float amax = sred[0];
    __syncthreads();

    // Seed scan: bins [slo, shi]
    const int slo = max(bin_of(amin) - SEED, 0);
    const int shi = min(bin_of(amax) + SEED, NBINS - 1);
    const float4* scatB = g_scat[cbB];
    scan_range(g_start[cbB][slo], g_start[cbB][shi + 1], scatB, tile, tid,
               axp, ayp, azp, eminE, eminO);

    // Bound: R = sqrt(max_i u_i)
    const float u = fmaxf(n1 + fminf(eminE, eminO), 0.0f);
    sred[tid] = u;
    __syncthreads();
    for (int w = NN_THREADS / 2; w > 0; w >>= 1) {
        if (tid < w) sred[tid] = fmaxf(sred[tid], sred[tid + w]);
        __syncthreads();
    }
    const float R = sqrtf(sred[0]);
    __syncthreads();

    // Residual scans: bins [flo, slo) and (shi, fhi]
    const int flo = bin_of(amin - R);
    const int fhi = bin_of(amax + R);
    if (flo < slo)
        scan_range(g_start[cbB][flo], g_start[cbB][slo], scatB, tile, tid,
                   axp, ayp, azp, eminE, eminO);
    if (fhi > shi)
        scan_range(g_start[cbB][shi + 1], g_start[cbB][fhi + 1], scatB, tile, tid,
                   axp, ayp, azp, eminE, eminO);

    const float d = fmaxf(n1 + fminf(eminE, eminO), 0.0f);
    float* __restrict__ outd = dir ? dist2 : dist1;
    outd[(size_t)b * Nc + oi] = d;
}

// ---------------- deterministic 2-stage loss reduction ----------------

__global__ void __launch_bounds__(256)
sum_stage1(const float* __restrict__ dists)   // dists = out+1, length 2*B*N
{
    __shared__ float red[256];
    const int tid = threadIdx.x;
    const int base = blockIdx.x * 1024;
    float s = 0.0f;
#pragma unroll
    for (int i = 0; i < 4; i++) s += dists[base + i * 256 + tid];
    red[tid] = s;
    __syncthreads();
    for (int w = 128; w > 0; w >>= 1) {
        if (tid < w) red[tid] += red[tid + w];
        __syncthreads();
    }
    if (tid == 0) g_partials[blockIdx.x] = red[0];
}

__global__ void __launch_bounds__(128)
sum_stage2(float* __restrict__ out)
{
    __shared__ float red[128];
    const int tid = threadIdx.x;
    red[tid] = g_partials[tid];
    __syncthreads();
    for (int w = 64; w > 0; w >>= 1) {
        if (tid < w) red[tid] += red[tid + w];
        __syncthreads();
    }
    if (tid == 0) out[0] = red[0] * (1.0f / (float)(Bc * Nc));
}

extern "C" void kernel_launch(void* const* d_in, const int* in_sizes, int n_in,
                              void* d_out, int out_size)
{
    const float* x1 = (const float*)d_in[0];
    const float* x2 = (const float*)d_in[1];
    float* out = (float*)d_out;
    float* dist1 = out + 1;
    float* dist2 = out + 1 + Bc * Nc;

    zero_kernel<<<1, 512>>>();
    hist_kernel<<<256, 512>>>(x1, x2);
    prefix_kernel<<<1, 512>>>();
    scatter_kernel<<<256, 512>>>(x1, x2);
    nn_kernel<<<NN_GRID, NN_THREADS>>>(dist1, dist2);

    sum_stage1<<<128, 256>>>(out + 1);
    sum_stage2<<<1, 128>>>(out);
}

// round 10
// speedup vs baseline: 1.5358x; 1.5358x over previous
#include <cuda_runtime.h>
#include <math_constants.h>

// ChamferDistance: x1,x2 = [B=8, N=M=8192, 3] fp32.
// out = [ loss (1) | dist1 (B*N) | dist2 (B*M) ]
//
// R10 = R6 (best known: 2 CTAs/SM via __launch_bounds__(512,2), single-barrier
// double-buffered 256-pt B tiles, 2048 balanced tiles, atomicMin combine,
// 0x7F sentinel fill) with the inner loop STAGE-GROUPED: the 4 k-chains issue
// stage-by-stage so consecutive FFMA2 share 2 of 3 source operands (operand
// reuse kills the 3-distinct-register bank penalty) and are mutually
// independent (perfect latency pipelining).

constexpr int Bc = 8;
constexpr int Nc = 8192;
constexpr int Mc = 8192;
constexpr int THREADS = 512;
constexpr int PTS = 4;                        // A-points per thread (each dup'd)
constexpr int TILE_N = THREADS * PTS;         // 2048
constexpr int NCHUNKS = Nc / TILE_N;          // 4
constexpr int TILE_M = 256;                   // B-points per slice
constexpr int JP = TILE_M / 2;                // 128 j-pairs
constexpr int MSLICES = Mc / TILE_M;          // 32
constexpr int NACH = 2 * Bc * NCHUNKS;        // 64 A-chunks
constexpr int NTILES = NACH * MSLICES;        // 2048
constexpr int GRID = 296;                     // 2 CTAs per SM

__device__ __forceinline__ unsigned long long pk2(float lo, float hi) {
    unsigned long long r;
    asm("mov.b64 %0, {%1, %2};" : "=l"(r) : "f"(lo), "f"(hi));
    return r;
}
__device__ __forceinline__ unsigned long long ffma2(unsigned long long a,
                                                    unsigned long long b,
                                                    unsigned long long c) {
    unsigned long long d;
    asm("fma.rn.f32x2 %0, %1, %2, %3;" : "=l"(d) : "l"(a), "l"(b), "l"(c));
    return d;
}
__device__ __forceinline__ void upk2(unsigned long long v, float& lo, float& hi) {
    asm("mov.b64 {%0, %1}, %2;" : "=f"(lo), "=f"(hi) : "l"(v));
}

// decode tile id -> (dir, b, nbase, ms)
__device__ __forceinline__ void decode_tile(int t, int& dir, int& b, int& nbase, int& ms) {
    const int ach = t >> 5;          // [0,64)
    ms = t & (MSLICES - 1);
    const int db = ach >> 2;         // dir*8 + b
    dir = db >> 3;
    b = db & 7;
    nbase = (ach & 3) * TILE_N;
}

__global__ void __launch_bounds__(THREADS, 2)
chamfer_pass_kernel(const float* __restrict__ x1, const float* __restrict__ x2,
                    float* __restrict__ dist1, float* __restrict__ dist2)
{
    // 2 buffers; per j-pair: {bx2_e,bx2_o, by2_e,by2_o, bz2_e,bz2_o, n2_e,n2_o}
    __shared__ __align__(16) float tile[2][JP * 8];

    const int tid = threadIdx.x;
    const int bid = blockIdx.x;
    const int tstart = (bid * NTILES) / GRID;
    const int tend   = ((bid + 1) * NTILES) / GRID;

    unsigned long long axp[PTS], ayp[PTS], azp[PTS];
    float n1s[PTS];
    float eminE[PTS], eminO[PTS];
    int cur_ach = -1;
    int cur_dir = 0, cur_b = 0, cur_nbase = 0;

    // prologue: fill buffer 0 with tile tstart
    {
        int dir, b, nbase, ms;
        decode_tile(tstart, dir, b, nbase, ms);
        const float* __restrict__ Q = dir ? x1 : x2;
        if (tid < JP) {
            const float* q = Q + ((size_t)b * Mc + ms * TILE_M + 2 * tid) * 3;
            const float bxe = q[0], bye = q[1], bze = q[2];
            const float bxo = q[3], byo = q[4], bzo = q[5];
            const float n2e = fmaf(bxe, bxe, fmaf(bye, bye, bze * bze));
            const float n2o = fmaf(bxo, bxo, fmaf(byo, byo, bzo * bzo));
            float4* s = reinterpret_cast<float4*>(&tile[0][tid * 8]);
            s[0] = make_float4(-2.0f * bxe, -2.0f * bxo, -2.0f * bye, -2.0f * byo);
            s[1] = make_float4(-2.0f * bze, -2.0f * bzo, n2e, n2o);
        }
    }

    for (int t = tstart; t < tend; t++) {
        const int buf = (t - tstart) & 1;

        // single barrier per round: orders this round's fill (done last round)
        // before compute, and last round's compute before we refill its buffer.
        __syncthreads();

        // fill NEXT tile into the other buffer
        if (t + 1 < tend && tid < JP) {
            int ndir, nb, nnbase, nms;
            decode_tile(t + 1, ndir, nb, nnbase, nms);
            const float* __restrict__ Q = ndir ? x1 : x2;
            const float* q = Q + ((size_t)nb * Mc + nms * TILE_M + 2 * tid) * 3;
            const float bxe = q[0], bye = q[1], bze = q[2];
            const float bxo = q[3], byo = q[4], bzo = q[5];
            const float n2e = fmaf(bxe, bxe, fmaf(bye, bye, bze * bze));
            const float n2o = fmaf(bxo, bxo, fmaf(byo, byo, bzo * bzo));
            float4* s = reinterpret_cast<float4*>(&tile[buf ^ 1][tid * 8]);
            s[0] = make_float4(-2.0f * bxe, -2.0f * bxo, -2.0f * bye, -2.0f * byo);
            s[1] = make_float4(-2.0f * bze, -2.0f * bzo, n2e, n2o);
        }

        // A-chunk management for CURRENT tile
        const int ach = t >> 5;
        if (ach != cur_ach) {
            if (cur_ach >= 0) {          // flush previous A-chunk
                float* __restrict__ outd = cur_dir ? dist2 : dist1;
#pragma unroll
                for (int k = 0; k < PTS; k++) {
                    const int n = cur_nbase + k * THREADS + tid;
                    const float e = fminf(eminE[k], eminO[k]);
                    const float d = fmaxf(n1s[k] + e, 0.0f);
                    atomicMin((int*)&outd[(size_t)cur_b * Nc + n], __float_as_int(d));
                }
            }
            cur_ach = ach;
            int ms_un;
            decode_tile(t, cur_dir, cur_b, cur_nbase, ms_un);
            const float* __restrict__ P = cur_dir ? x2 : x1;
#pragma unroll
            for (int k = 0; k < PTS; k++) {
                const int n = cur_nbase + k * THREADS + tid;
                const float* p = P + ((size_t)cur_b * Nc + n) * 3;
                const float ax = p[0], ay = p[1], az = p[2];
                axp[k] = pk2(ax, ax);
                ayp[k] = pk2(ay, ay);
                azp[k] = pk2(az, az);
                n1s[k] = fmaf(ax, ax, fmaf(ay, ay, az * az));
                eminE[k] = CUDART_INF_F;
                eminO[k] = CUDART_INF_F;
            }
        }

        // compute CURRENT buffer: stage-grouped so consecutive FFMA2 share
        // 2 of 3 operands (reuse) and are independent (different k chains).
        const ulonglong2* sp = reinterpret_cast<const ulonglong2*>(tile[buf]);
#pragma unroll 8
        for (int jj = 0; jj < JP; jj++) {
            const ulonglong2 c0 = sp[2 * jj];       // {bx2_e,bx2_o} {by2_e,by2_o}
            const ulonglong2 c1 = sp[2 * jj + 1];   // {bz2_e,bz2_o} {n2_e,n2_o}

            unsigned long long e0, e1, e2, e3;
            // stage 1: x terms — c0.x and c1.y shared across all 4
            e0 = ffma2(axp[0], c0.x, c1.y);
            e1 = ffma2(axp[1], c0.x, c1.y);
            e2 = ffma2(axp[2], c0.x, c1.y);
            e3 = ffma2(axp[3], c0.x, c1.y);
            // stage 2: y terms — c0.y shared
            e0 = ffma2(ayp[0], c0.y, e0);
            e1 = ffma2(ayp[1], c0.y, e1);
            e2 = ffma2(ayp[2], c0.y, e2);
            e3 = ffma2(ayp[3], c0.y, e3);
            // stage 3: z terms — c1.x shared
            e0 = ffma2(azp[0], c1.x, e0);
            e1 = ffma2(azp[1], c1.x, e1);
            e2 = ffma2(azp[2], c1.x, e2);
            e3 = ffma2(azp[3], c1.x, e3);
            // stage 4: mins (alu pipe, overlaps next jj's ffma stream)
            float f0lo, f0hi, f1lo, f1hi, f2lo, f2hi, f3lo, f3hi;
            upk2(e0, f0lo, f0hi);
            upk2(e1, f1lo, f1hi);
            upk2(e2, f2lo, f2hi);
            upk2(e3, f3lo, f3hi);
            eminE[0] = fminf(eminE[0], f0lo);
            eminO[0] = fminf(eminO[0], f0hi);
            eminE[1] = fminf(eminE[1], f1lo);
            eminO[1] = fminf(eminO[1], f1hi);
            eminE[2] = fminf(eminE[2], f2lo);
            eminO[2] = fminf(eminO[2], f2hi);
            eminE[3] = fminf(eminE[3], f3lo);
            eminO[3] = fminf(eminO[3], f3hi);
        }
    }

    if (cur_ach >= 0) {                  // final flush
        float* __restrict__ outd = cur_dir ? dist2 : dist1;
#pragma unroll
        for (int k = 0; k < PTS; k++) {
            const int n = cur_nbase + k * THREADS + tid;
            const float e = fminf(eminE[k], eminO[k]);
            const float d = fmaxf(n1s[k] + e, 0.0f);
            atomicMin((int*)&outd[(size_t)cur_b * Nc + n], __float_as_int(d));
        }
    }
}

// ---- deterministic 2-stage loss reduction ----
__device__ float g_partials[128];

__global__ void __launch_bounds__(256)
sum_stage1(const float* __restrict__ dists)   // dists = out+1, length 2*B*N
{
    __shared__ float red[256];
    const int tid = threadIdx.x;
    const int base = blockIdx.x * 1024;
    float s = 0.0f;
#pragma unroll
    for (int i = 0; i < 4; i++) s += dists[base + i * 256 + tid];
    red[tid] = s;
    __syncthreads();
    for (int w = 128; w > 0; w >>= 1) {
        if (tid < w) red[tid] += red[tid + w];
        __syncthreads();
    }
    if (tid == 0) g_partials[blockIdx.x] = red[0];
}

__global__ void __launch_bounds__(128)
sum_stage2(float* __restrict__ out)
{
    __shared__ float red[128];
    const int tid = threadIdx.x;
    red[tid] = g_partials[tid];
    __syncthreads();
    for (int w = 64; w > 0; w >>= 1) {
        if (tid < w) red[tid] += red[tid + w];
        __syncthreads();
    }
    if (tid == 0) out[0] = red[0] * (1.0f / (float)(Bc * Nc));
}

extern "C" void kernel_launch(void* const* d_in, const int* in_sizes, int n_in,
                              void* d_out, int out_size)
{
    const float* x1 = (const float*)d_in[0];
    const float* x2 = (const float*)d_in[1];
    float* out = (float*)d_out;
    float* dist1 = out + 1;
    float* dist2 = out + 1 + Bc * Nc;

    // Sentinel-fill dist arrays: 0x7F7F7F7F = 3.39e38 > any real sq-distance.
    cudaMemsetAsync(out + 1, 0x7F, (size_t)2 * Bc * Nc * sizeof(float));

    chamfer_pass_kernel<<<GRID, THREADS>>>(x1, x2, dist1, dist2);

    sum_stage1<<<128, 256>>>(out + 1);
    sum_stage2<<<1, 128>>>(out);
}